// round 2
// baseline (speedup 1.0000x reference)
#include <cuda_runtime.h>

// Problem-fixed sizes
static constexpr int NN = 253952;
static constexpr int EE = 4000000;
static constexpr int NG = 4096;

// Scratch (static __device__ arrays — no allocation)
__device__ float g_bufA[(size_t)NN * 64];   // aggregation buffer (ping)
__device__ float g_bufB[(size_t)NN * 64];   // hidden buffer (pong)
__device__ int   g_src[EE];
__device__ int   g_dst[EE];
__device__ int   g_batch[NN];
__device__ float g_pool[NG * 52];
__device__ int   g_flags[2];                // [0]=edge_index is int64, [1]=batch is int64

__device__ __forceinline__ float lrelu(float v) { return v > 0.0f ? v : v * 0.01f; }

// ---------------------------------------------------------------------------
// Dtype detection: int64 little-endian values < 2^31 have zero high words.
// Probe odd-index 32-bit words in windows valid under BOTH interpretations.
// ---------------------------------------------------------------------------
__global__ void k_detect(const int* __restrict__ ei_raw, const int* __restrict__ b_raw,
                         int E, int N) {
    if (blockIdx.x != 0 || threadIdx.x != 0) return;
    // edge_index: int32 view has 2E words; window [E, E+256) is in-bounds either way.
    int acc = 0;
    for (int i = 1; i < 256; i += 2) acc |= ei_raw[E + i];
    g_flags[0] = (acc == 0) ? 1 : 0;
    // batch: int32 view has N words; probe near N/2 (values ~2048, nonzero).
    int base = (N / 2) & ~1;
    int acc2 = 0;
    for (int i = 1; i < 256; i += 2) acc2 |= b_raw[base + i];
    g_flags[1] = (acc2 == 0) ? 1 : 0;
}

// ---------------------------------------------------------------------------
// Prep: edge index -> int32, batch -> int32, pad x [N,6] -> [N,8]
// ---------------------------------------------------------------------------
__global__ void k_prep(const void* __restrict__ ei_raw, const void* __restrict__ b_raw,
                       const float* __restrict__ x,
                       int* __restrict__ src, int* __restrict__ dst,
                       int* __restrict__ batch32,
                       float* __restrict__ xpad, int N, int E) {
    int i = blockIdx.x * blockDim.x + threadIdx.x;
    bool ei64 = g_flags[0] != 0;
    bool b64 = g_flags[1] != 0;
    if (i < E) {
        if (ei64) {
            const long long* p = (const long long*)ei_raw;
            src[i] = (int)p[i];
            dst[i] = (int)p[(size_t)E + i];
        } else {
            const int* p = (const int*)ei_raw;
            src[i] = p[i];
            dst[i] = p[(size_t)E + i];
        }
    }
    if (i < N) {
        batch32[i] = b64 ? (int)((const long long*)b_raw)[i] : ((const int*)b_raw)[i];
        const float* xr = x + (size_t)i * 6;
        float* o = xpad + (size_t)i * 8;
        o[0] = xr[0]; o[1] = xr[1]; o[2] = xr[2];
        o[3] = xr[3]; o[4] = xr[4]; o[5] = xr[5];
        o[6] = 0.0f;  o[7] = 0.0f;
    }
}

// ---------------------------------------------------------------------------
// Zero fill (float4)
// ---------------------------------------------------------------------------
__global__ void k_zero(float4* __restrict__ p, int n4) {
    int i = blockIdx.x * blockDim.x + threadIdx.x;
    if (i < n4) p[i] = make_float4(0.f, 0.f, 0.f, 0.f);
}

// ---------------------------------------------------------------------------
// Edge scatter: agg[dst] += h[src] * ew   (DIM floats per node, DIM/4 thr/edge)
// ---------------------------------------------------------------------------
template <int DIM>
__global__ void k_scatter(const float* __restrict__ h,
                          const int* __restrict__ src, const int* __restrict__ dst,
                          const float* __restrict__ ew,
                          float* __restrict__ agg, int E) {
    constexpr int T = DIM / 4;
    long long t = (long long)blockIdx.x * blockDim.x + threadIdx.x;
    int e = (int)(t / T);
    int g = (int)(t % T);
    if (e >= E) return;
    int s = __ldg(&src[e]);
    int d = __ldg(&dst[e]);
    float w = __ldg(&ew[e]);
    float4 hv = *reinterpret_cast<const float4*>(h + (size_t)s * DIM + g * 4);
    float4 m = make_float4(hv.x * w, hv.y * w, hv.z * w, hv.w * w);
    atomicAdd(reinterpret_cast<float4*>(agg + (size_t)d * DIM + g * 4), m);
}

// ---------------------------------------------------------------------------
// Node transform: out = lrelu(agg @ W + b)   W [IN, OUT] row-major.
// ---------------------------------------------------------------------------
template <int IN, int INS, int OUT, int OUTS, bool DBL>
__global__ void k_transform(const float* __restrict__ agg,
                            const float* __restrict__ W, const float* __restrict__ b,
                            float* __restrict__ out, int N) {
    __shared__ float sW[IN * OUT];
    __shared__ float sb[OUT];
    for (int i = threadIdx.x; i < IN * OUT; i += blockDim.x) sW[i] = W[i];
    for (int i = threadIdx.x; i < OUT; i += blockDim.x) sb[i] = b[i];
    __syncthreads();
    int n = blockIdx.x * blockDim.x + threadIdx.x;
    if (n >= N) return;
    float a[IN];
#pragma unroll
    for (int k = 0; k < IN; k++) a[k] = agg[(size_t)n * INS + k];
    float* orow = out + (size_t)n * OUTS;
    for (int of = 0; of < OUT; of++) {
        float acc = sb[of];
#pragma unroll
        for (int k = 0; k < IN; k++) acc += a[k] * sW[k * OUT + of];
        acc = lrelu(acc);
        if (DBL) acc = lrelu(acc);
        orow[of] = acc;
    }
    for (int of = OUT; of < OUTS; of++) orow[of] = 0.0f;
}

// ---------------------------------------------------------------------------
// Pool: pooled[batch[n]] += h[n]  (h stride 52; batch sorted -> run-length
// accumulate locally, flush atomics only on boundaries)
// ---------------------------------------------------------------------------
__global__ void k_pool(const float* __restrict__ h, const int* __restrict__ batch,
                       float* __restrict__ pooled, int N) {
    int g = blockIdx.y;                                   // 0..12 feature group
    int chunk = blockIdx.x * blockDim.x + threadIdx.x;    // 64-node chunk
    int n0 = chunk * 64;
    if (n0 >= N) return;
    int n1 = min(n0 + 64, N);
    int cur = batch[n0];
    float4 acc = make_float4(0.f, 0.f, 0.f, 0.f);
    for (int n = n0; n < n1; n++) {
        int bg = batch[n];
        if (bg != cur) {
            atomicAdd(reinterpret_cast<float4*>(pooled + (size_t)cur * 52 + g * 4), acc);
            acc = make_float4(0.f, 0.f, 0.f, 0.f);
            cur = bg;
        }
        float4 v = *reinterpret_cast<const float4*>(h + (size_t)n * 52 + g * 4);
        acc.x += v.x; acc.y += v.y; acc.z += v.z; acc.w += v.w;
    }
    atomicAdd(reinterpret_cast<float4*>(pooled + (size_t)cur * 52 + g * 4), acc);
}

// ---------------------------------------------------------------------------
// MLP head: [G,50] -> 30 -> 20 -> 2, lrelu each, one thread per graph
// ---------------------------------------------------------------------------
__global__ void k_fc(const float* __restrict__ pooled,
                     const float* __restrict__ W1, const float* __restrict__ b1,
                     const float* __restrict__ W2, const float* __restrict__ b2,
                     const float* __restrict__ W3, const float* __restrict__ b3,
                     float* __restrict__ out) {
    __shared__ float s1[50 * 30], s2[30 * 20], s3[20 * 2];
    __shared__ float t1[30], t2[20], t3[2];
    for (int i = threadIdx.x; i < 50 * 30; i += blockDim.x) s1[i] = W1[i];
    for (int i = threadIdx.x; i < 30 * 20; i += blockDim.x) s2[i] = W2[i];
    for (int i = threadIdx.x; i < 20 * 2; i += blockDim.x) s3[i] = W3[i];
    if (threadIdx.x < 30) t1[threadIdx.x] = b1[threadIdx.x];
    if (threadIdx.x < 20) t2[threadIdx.x] = b2[threadIdx.x];
    if (threadIdx.x < 2) t3[threadIdx.x] = b3[threadIdx.x];
    __syncthreads();
    int gi = blockIdx.x * blockDim.x + threadIdx.x;
    if (gi >= NG) return;
    float p[50];
#pragma unroll
    for (int k = 0; k < 50; k++) p[k] = pooled[(size_t)gi * 52 + k];
    float a1[30];
    for (int of = 0; of < 30; of++) {
        float acc = t1[of];
#pragma unroll
        for (int k = 0; k < 50; k++) acc += p[k] * s1[k * 30 + of];
        a1[of] = lrelu(acc);
    }
    float a2[20];
    for (int of = 0; of < 20; of++) {
        float acc = t2[of];
#pragma unroll
        for (int k = 0; k < 30; k++) acc += a1[k] * s2[k * 20 + of];
        a2[of] = lrelu(acc);
    }
#pragma unroll
    for (int of = 0; of < 2; of++) {
        float acc = t3[of];
#pragma unroll
        for (int k = 0; k < 20; k++) acc += a2[k] * s3[k * 2 + of];
        out[(size_t)gi * 2 + of] = lrelu(acc);
    }
}

// ---------------------------------------------------------------------------
extern "C" void kernel_launch(void* const* d_in, const int* in_sizes, int n_in,
                              void* d_out, int out_size) {
    const float* x     = (const float*)d_in[0];
    const void*  ei    = d_in[1];
    const float* ew    = (const float*)d_in[2];
    const void*  batch = d_in[3];
    const float* W1 = (const float*)d_in[4];  const float* b1 = (const float*)d_in[5];
    const float* W2 = (const float*)d_in[6];  const float* b2 = (const float*)d_in[7];
    const float* W3 = (const float*)d_in[8];  const float* b3 = (const float*)d_in[9];
    const float* W4 = (const float*)d_in[10]; const float* b4 = (const float*)d_in[11];
    const float* Wf1 = (const float*)d_in[12]; const float* bf1 = (const float*)d_in[13];
    const float* Wf2 = (const float*)d_in[14]; const float* bf2 = (const float*)d_in[15];
    const float* Wf3 = (const float*)d_in[16]; const float* bf3 = (const float*)d_in[17];
    float* out = (float*)d_out;

    int N = in_sizes[0] / 6;
    int E = in_sizes[2];

    float *bufA, *bufB, *pool;
    int *src, *dst, *batch32;
    cudaGetSymbolAddress((void**)&bufA, g_bufA);
    cudaGetSymbolAddress((void**)&bufB, g_bufB);
    cudaGetSymbolAddress((void**)&pool, g_pool);
    cudaGetSymbolAddress((void**)&src, g_src);
    cudaGetSymbolAddress((void**)&dst, g_dst);
    cudaGetSymbolAddress((void**)&batch32, g_batch);

    const int BT = 256;
    k_detect<<<1, 32>>>((const int*)ei, (const int*)batch, E, N);
    int mx = E > N ? E : N;
    k_prep<<<(mx + BT - 1) / BT, BT>>>(ei, batch, x, src, dst, batch32, bufB, N, E);

    // ---- Layer 1: scatter dim 8 (x padded), transform 6->16
    {
        int n4 = N * 8 / 4;
        k_zero<<<(n4 + BT - 1) / BT, BT>>>((float4*)bufA, n4);
        long long th = (long long)E * 2;
        k_scatter<8><<<(unsigned)((th + BT - 1) / BT), BT>>>(bufB, src, dst, ew, bufA, E);
        k_transform<6, 8, 16, 16, false><<<(N + 127) / 128, 128>>>(bufA, W1, b1, bufB, N);
    }
    // ---- Layer 2: scatter dim 16, transform 16->32
    {
        int n4 = N * 16 / 4;
        k_zero<<<(n4 + BT - 1) / BT, BT>>>((float4*)bufA, n4);
        long long th = (long long)E * 4;
        k_scatter<16><<<(unsigned)((th + BT - 1) / BT), BT>>>(bufB, src, dst, ew, bufA, E);
        k_transform<16, 16, 32, 32, false><<<(N + 127) / 128, 128>>>(bufA, W2, b2, bufB, N);
    }
    // ---- Layer 3: scatter dim 32, transform 32->64
    {
        int n4 = N * 32 / 4;
        k_zero<<<(n4 + BT - 1) / BT, BT>>>((float4*)bufA, n4);
        long long th = (long long)E * 8;
        k_scatter<32><<<(unsigned)((th + BT - 1) / BT), BT>>>(bufB, src, dst, ew, bufA, E);
        k_transform<32, 32, 64, 64, false><<<(N + 127) / 128, 128>>>(bufA, W3, b3, bufB, N);
    }
    // ---- Layer 4: scatter dim 64, transform 64->50 (double lrelu), stride 52
    {
        int n4 = N * 64 / 4;
        k_zero<<<(n4 + BT - 1) / BT, BT>>>((float4*)bufA, n4);
        long long th = (long long)E * 16;
        k_scatter<64><<<(unsigned)((th + BT - 1) / BT), BT>>>(bufB, src, dst, ew, bufA, E);
        k_transform<64, 64, 50, 52, true><<<(N + 127) / 128, 128>>>(bufA, W4, b4, bufB, N);
    }
    // ---- Pool
    {
        int n4 = NG * 52 / 4;
        k_zero<<<(n4 + BT - 1) / BT, BT>>>((float4*)pool, n4);
        int chunks = (N + 63) / 64;
        dim3 grid((chunks + 127) / 128, 13);
        k_pool<<<grid, 128>>>(bufB, batch32, pool, N);
    }
    // ---- MLP head
    k_fc<<<(NG + BT - 1) / BT, BT>>>(pool, Wf1, bf1, Wf2, bf2, Wf3, bf3, out);
}

// round 3
// speedup vs baseline: 1.9555x; 1.9555x over previous
#include <cuda_runtime.h>

// Problem-fixed sizes
static constexpr int NN = 253952;
static constexpr int EE = 4000000;
static constexpr int NG = 4096;
static constexpr int SCAN_BS = 1024;
static constexpr int MAXPART = (NN + SCAN_BS - 1) / SCAN_BS + 2;

// Scratch (static __device__ arrays — no allocation)
__device__ float g_bufA[(size_t)NN * 64];
__device__ float g_bufB[(size_t)NN * 64];
__device__ int   g_src[EE];
__device__ int   g_dst[EE];
__device__ int2  g_csr[EE];          // packed (src, weight-bits), grouped by dst
__device__ int   g_deg[NN];
__device__ int   g_tmp[NN];
__device__ int   g_rp[NN + 1];
__device__ int   g_cur[NN];
__device__ int   g_part[MAXPART];
__device__ int   g_batch[NN];
__device__ float g_pool[NG * 52];
__device__ int   g_flags[2];

__device__ __forceinline__ float lrelu(float v) { return v > 0.0f ? v : v * 0.01f; }

// ---------------------------------------------------------------------------
// Dtype detection (int64 little-endian high words are zero)
// ---------------------------------------------------------------------------
__global__ void k_detect(const int* __restrict__ ei_raw, const int* __restrict__ b_raw,
                         int E, int N) {
    if (blockIdx.x != 0 || threadIdx.x != 0) return;
    int acc = 0;
    for (int i = 1; i < 256; i += 2) acc |= ei_raw[E + i];
    g_flags[0] = (acc == 0) ? 1 : 0;
    int base = (N / 2) & ~1;
    int acc2 = 0;
    for (int i = 1; i < 256; i += 2) acc2 |= b_raw[base + i];
    g_flags[1] = (acc2 == 0) ? 1 : 0;
}

// ---------------------------------------------------------------------------
// Prep: convert indices, pad x [N,6]->[N,8], zero deg
// ---------------------------------------------------------------------------
__global__ void k_prep(const void* __restrict__ ei_raw, const void* __restrict__ b_raw,
                       const float* __restrict__ x,
                       int* __restrict__ src, int* __restrict__ dst,
                       int* __restrict__ batch32, int* __restrict__ deg,
                       float* __restrict__ xpad, int N, int E) {
    int i = blockIdx.x * blockDim.x + threadIdx.x;
    bool ei64 = g_flags[0] != 0;
    bool b64 = g_flags[1] != 0;
    if (i < E) {
        if (ei64) {
            const long long* p = (const long long*)ei_raw;
            src[i] = (int)p[i];
            dst[i] = (int)p[(size_t)E + i];
        } else {
            const int* p = (const int*)ei_raw;
            src[i] = p[i];
            dst[i] = p[(size_t)E + i];
        }
    }
    if (i < N) {
        deg[i] = 0;
        batch32[i] = b64 ? (int)((const long long*)b_raw)[i] : ((const int*)b_raw)[i];
        const float* xr = x + (size_t)i * 6;
        float* o = xpad + (size_t)i * 8;
        o[0] = xr[0]; o[1] = xr[1]; o[2] = xr[2];
        o[3] = xr[3]; o[4] = xr[4]; o[5] = xr[5];
        o[6] = 0.0f;  o[7] = 0.0f;
    }
}

// ---------------------------------------------------------------------------
// CSR build: histogram -> 2-level exclusive scan -> fill
// ---------------------------------------------------------------------------
__global__ void k_hist(const int* __restrict__ dst, int* __restrict__ deg, int E) {
    int e = blockIdx.x * blockDim.x + threadIdx.x;
    if (e < E) atomicAdd(&deg[dst[e]], 1);
}

__global__ void k_scan1(const int* __restrict__ deg, int* __restrict__ tmp,
                        int* __restrict__ part, int N) {
    __shared__ int s[SCAN_BS];
    int i = blockIdx.x * SCAN_BS + threadIdx.x;
    int v = (i < N) ? deg[i] : 0;
    s[threadIdx.x] = v;
    __syncthreads();
    for (int off = 1; off < SCAN_BS; off <<= 1) {
        int add = (threadIdx.x >= off) ? s[threadIdx.x - off] : 0;
        __syncthreads();
        s[threadIdx.x] += add;
        __syncthreads();
    }
    if (i < N) tmp[i] = s[threadIdx.x];                 // inclusive
    if (threadIdx.x == SCAN_BS - 1) part[blockIdx.x] = s[threadIdx.x];
}

__global__ void k_scan2(int* __restrict__ part, int nb) {
    if (threadIdx.x != 0 || blockIdx.x != 0) return;
    int run = 0;
    for (int b = 0; b < nb; b++) { int v = part[b]; part[b] = run; run += v; }
}

__global__ void k_scan3(const int* __restrict__ tmp, const int* __restrict__ deg,
                        const int* __restrict__ part,
                        int* __restrict__ rp, int* __restrict__ cur, int N, int E) {
    int i = blockIdx.x * blockDim.x + threadIdx.x;
    if (i < N) {
        int excl = tmp[i] - deg[i] + part[i / SCAN_BS];
        rp[i] = excl;
        cur[i] = excl;
    }
    if (i == 0) rp[N] = E;
}

__global__ void k_fill(const int* __restrict__ src, const int* __restrict__ dst,
                       const float* __restrict__ ew,
                       int* __restrict__ cur, int2* __restrict__ csr, int E) {
    int e = blockIdx.x * blockDim.x + threadIdx.x;
    if (e >= E) return;
    int d = dst[e];
    int pos = atomicAdd(&cur[d], 1);
    csr[pos] = make_int2(src[e], __float_as_int(ew[e]));
}

// ---------------------------------------------------------------------------
// Pull aggregation: agg[n] = sum_{e in-edges} h[src_e] * w_e  (no atomics)
// thread = (node, f4-group); STRIDE floats per row, T = STRIDE/4 groups.
// ---------------------------------------------------------------------------
template <int STRIDE>
__global__ void k_pull(const float* __restrict__ h, const int2* __restrict__ csr,
                       const int* __restrict__ rp, float* __restrict__ agg, int N) {
    constexpr int T = STRIDE / 4;
    int t = blockIdx.x * blockDim.x + threadIdx.x;
    int node = t / T;
    int g = t % T;
    if (node >= N) return;
    int e = __ldg(&rp[node]);
    int end = __ldg(&rp[node + 1]);
    float4 acc = make_float4(0.f, 0.f, 0.f, 0.f);
    for (; e + 1 < end; e += 2) {
        int2 p0 = __ldg(&csr[e]);
        int2 p1 = __ldg(&csr[e + 1]);
        float w0 = __int_as_float(p0.y);
        float w1 = __int_as_float(p1.y);
        float4 a = __ldg(reinterpret_cast<const float4*>(h + (size_t)p0.x * STRIDE + g * 4));
        float4 b = __ldg(reinterpret_cast<const float4*>(h + (size_t)p1.x * STRIDE + g * 4));
        acc.x += a.x * w0 + b.x * w1;
        acc.y += a.y * w0 + b.y * w1;
        acc.z += a.z * w0 + b.z * w1;
        acc.w += a.w * w0 + b.w * w1;
    }
    if (e < end) {
        int2 p0 = __ldg(&csr[e]);
        float w0 = __int_as_float(p0.y);
        float4 a = __ldg(reinterpret_cast<const float4*>(h + (size_t)p0.x * STRIDE + g * 4));
        acc.x += a.x * w0; acc.y += a.y * w0; acc.z += a.z * w0; acc.w += a.w * w0;
    }
    *reinterpret_cast<float4*>(agg + (size_t)node * STRIDE + g * 4) = acc;
}

// ---------------------------------------------------------------------------
// Node transform: out = act(agg @ W (+b)); pads zeroed. W [IN, OUT] row-major.
// ---------------------------------------------------------------------------
template <int IN, int INS, int OUT, int OUTS, bool BIAS, bool ACT>
__global__ void k_transform(const float* __restrict__ agg,
                            const float* __restrict__ W, const float* __restrict__ b,
                            float* __restrict__ out, int N) {
    __shared__ float sW[IN * OUT];
    __shared__ float sb[OUT];
    for (int i = threadIdx.x; i < IN * OUT; i += blockDim.x) sW[i] = W[i];
    if (BIAS)
        for (int i = threadIdx.x; i < OUT; i += blockDim.x) sb[i] = b[i];
    __syncthreads();
    int n = blockIdx.x * blockDim.x + threadIdx.x;
    if (n >= N) return;
    float a[IN];
#pragma unroll
    for (int k = 0; k < IN; k++) a[k] = agg[(size_t)n * INS + k];
    float* orow = out + (size_t)n * OUTS;
    for (int of = 0; of < OUT; of++) {
        float acc = BIAS ? sb[of] : 0.0f;
#pragma unroll
        for (int k = 0; k < IN; k++) acc += a[k] * sW[k * OUT + of];
        if (ACT) acc = lrelu(acc);
        orow[of] = acc;
    }
    for (int of = OUT; of < OUTS; of++) orow[of] = 0.0f;
}

// ---------------------------------------------------------------------------
// Pool with fused layer-4 bias + double lrelu:
// pooled[batch[n]] += f(agg4[n]) where f(v)=lrelu(lrelu(v + b4)) on cols<50
// batch sorted -> run-length local accumulation, atomics on boundaries only.
// ---------------------------------------------------------------------------
__global__ void k_pool(const float* __restrict__ h, const int* __restrict__ batch,
                       const float* __restrict__ b4,
                       float* __restrict__ pooled, int N) {
    int g = blockIdx.y;                                   // 0..12 feature group
    int c0 = g * 4;
    float bx = (c0 + 0 < 50) ? b4[c0 + 0] : 0.f;
    float by = (c0 + 1 < 50) ? b4[c0 + 1] : 0.f;
    float bz = (c0 + 2 < 50) ? b4[c0 + 2] : 0.f;
    float bw = (c0 + 3 < 50) ? b4[c0 + 3] : 0.f;
    int chunk = blockIdx.x * blockDim.x + threadIdx.x;
    int n0 = chunk * 64;
    if (n0 >= N) return;
    int n1 = min(n0 + 64, N);
    int cur = batch[n0];
    float4 acc = make_float4(0.f, 0.f, 0.f, 0.f);
    for (int n = n0; n < n1; n++) {
        int bg = batch[n];
        if (bg != cur) {
            atomicAdd(reinterpret_cast<float4*>(pooled + (size_t)cur * 52 + c0), acc);
            acc = make_float4(0.f, 0.f, 0.f, 0.f);
            cur = bg;
        }
        float4 v = *reinterpret_cast<const float4*>(h + (size_t)n * 52 + c0);
        if (c0 + 0 < 50) acc.x += lrelu(lrelu(v.x + bx));
        if (c0 + 1 < 50) acc.y += lrelu(lrelu(v.y + by));
        if (c0 + 2 < 50) acc.z += lrelu(lrelu(v.z + bz));
        if (c0 + 3 < 50) acc.w += lrelu(lrelu(v.w + bw));
    }
    atomicAdd(reinterpret_cast<float4*>(pooled + (size_t)cur * 52 + c0), acc);
}

// ---------------------------------------------------------------------------
// Zero fill (float4)
// ---------------------------------------------------------------------------
__global__ void k_zero(float4* __restrict__ p, int n4) {
    int i = blockIdx.x * blockDim.x + threadIdx.x;
    if (i < n4) p[i] = make_float4(0.f, 0.f, 0.f, 0.f);
}

// ---------------------------------------------------------------------------
// MLP head: [G,50] -> 30 -> 20 -> 2
// ---------------------------------------------------------------------------
__global__ void k_fc(const float* __restrict__ pooled,
                     const float* __restrict__ W1, const float* __restrict__ b1,
                     const float* __restrict__ W2, const float* __restrict__ b2,
                     const float* __restrict__ W3, const float* __restrict__ b3,
                     float* __restrict__ out) {
    __shared__ float s1[50 * 30], s2[30 * 20], s3[20 * 2];
    __shared__ float t1[30], t2[20], t3[2];
    for (int i = threadIdx.x; i < 50 * 30; i += blockDim.x) s1[i] = W1[i];
    for (int i = threadIdx.x; i < 30 * 20; i += blockDim.x) s2[i] = W2[i];
    for (int i = threadIdx.x; i < 20 * 2; i += blockDim.x) s3[i] = W3[i];
    if (threadIdx.x < 30) t1[threadIdx.x] = b1[threadIdx.x];
    if (threadIdx.x < 20) t2[threadIdx.x] = b2[threadIdx.x];
    if (threadIdx.x < 2) t3[threadIdx.x] = b3[threadIdx.x];
    __syncthreads();
    int gi = blockIdx.x * blockDim.x + threadIdx.x;
    if (gi >= NG) return;
    float p[50];
#pragma unroll
    for (int k = 0; k < 50; k++) p[k] = pooled[(size_t)gi * 52 + k];
    float a1[30];
    for (int of = 0; of < 30; of++) {
        float acc = t1[of];
#pragma unroll
        for (int k = 0; k < 50; k++) acc += p[k] * s1[k * 30 + of];
        a1[of] = lrelu(acc);
    }
    float a2[20];
    for (int of = 0; of < 20; of++) {
        float acc = t2[of];
#pragma unroll
        for (int k = 0; k < 30; k++) acc += a1[k] * s2[k * 20 + of];
        a2[of] = lrelu(acc);
    }
#pragma unroll
    for (int of = 0; of < 2; of++) {
        float acc = t3[of];
#pragma unroll
        for (int k = 0; k < 20; k++) acc += a2[k] * s3[k * 2 + of];
        out[(size_t)gi * 2 + of] = lrelu(acc);
    }
}

// ---------------------------------------------------------------------------
extern "C" void kernel_launch(void* const* d_in, const int* in_sizes, int n_in,
                              void* d_out, int out_size) {
    const float* x     = (const float*)d_in[0];
    const void*  ei    = d_in[1];
    const float* ew    = (const float*)d_in[2];
    const void*  batch = d_in[3];
    const float* W1 = (const float*)d_in[4];  const float* b1 = (const float*)d_in[5];
    const float* W2 = (const float*)d_in[6];  const float* b2 = (const float*)d_in[7];
    const float* W3 = (const float*)d_in[8];  const float* b3 = (const float*)d_in[9];
    const float* W4 = (const float*)d_in[10]; const float* b4 = (const float*)d_in[11];
    const float* Wf1 = (const float*)d_in[12]; const float* bf1 = (const float*)d_in[13];
    const float* Wf2 = (const float*)d_in[14]; const float* bf2 = (const float*)d_in[15];
    const float* Wf3 = (const float*)d_in[16]; const float* bf3 = (const float*)d_in[17];
    float* out = (float*)d_out;

    int N = in_sizes[0] / 6;
    int E = in_sizes[2];

    float *bufA, *bufB, *pool;
    int *src, *dst, *batch32, *deg, *tmp, *rp, *cur, *part;
    int2* csr;
    cudaGetSymbolAddress((void**)&bufA, g_bufA);
    cudaGetSymbolAddress((void**)&bufB, g_bufB);
    cudaGetSymbolAddress((void**)&pool, g_pool);
    cudaGetSymbolAddress((void**)&src, g_src);
    cudaGetSymbolAddress((void**)&dst, g_dst);
    cudaGetSymbolAddress((void**)&batch32, g_batch);
    cudaGetSymbolAddress((void**)&deg, g_deg);
    cudaGetSymbolAddress((void**)&tmp, g_tmp);
    cudaGetSymbolAddress((void**)&rp, g_rp);
    cudaGetSymbolAddress((void**)&cur, g_cur);
    cudaGetSymbolAddress((void**)&part, g_part);
    cudaGetSymbolAddress((void**)&csr, g_csr);

    const int BT = 256;
    int nb = (N + SCAN_BS - 1) / SCAN_BS;

    k_detect<<<1, 32>>>((const int*)ei, (const int*)batch, E, N);
    int mx = E > N ? E : N;
    k_prep<<<(mx + BT - 1) / BT, BT>>>(ei, batch, x, src, dst, batch32, deg, bufB, N, E);

    // CSR build
    k_hist<<<(E + BT - 1) / BT, BT>>>(dst, deg, E);
    k_scan1<<<nb, SCAN_BS>>>(deg, tmp, part, N);
    k_scan2<<<1, 32>>>(part, nb);
    k_scan3<<<(N + BT - 1) / BT, BT>>>(tmp, deg, part, rp, cur, N, E);
    k_fill<<<(E + BT - 1) / BT, BT>>>(src, dst, ew, cur, csr, E);

    // ---- Layer 1: pull dim8, transform 6->16
    k_pull<8><<<((N * 2) + BT - 1) / BT, BT>>>(bufB, csr, rp, bufA, N);
    k_transform<6, 8, 16, 16, true, true><<<(N + 127) / 128, 128>>>(bufA, W1, b1, bufB, N);
    // ---- Layer 2: pull dim16, transform 16->32
    k_pull<16><<<((N * 4) + BT - 1) / BT, BT>>>(bufB, csr, rp, bufA, N);
    k_transform<16, 16, 32, 32, true, true><<<(N + 127) / 128, 128>>>(bufA, W2, b2, bufB, N);
    // ---- Layer 3: pull dim32, transform 32->64
    k_pull<32><<<((N * 8) + BT - 1) / BT, BT>>>(bufB, csr, rp, bufA, N);
    k_transform<32, 32, 64, 64, true, true><<<(N + 127) / 128, 128>>>(bufA, W3, b3, bufB, N);
    // ---- Layer 4: pre-transform 64->50 (linear, pad 52), pull dim52
    k_transform<64, 64, 50, 52, false, false><<<(N + 127) / 128, 128>>>(bufB, W4, nullptr, bufA, N);
    k_pull<52><<<((N * 13) + BT - 1) / BT, BT>>>(bufA, csr, rp, bufB, N);

    // ---- Pool (fused bias + double lrelu)
    {
        int n4 = NG * 52 / 4;
        k_zero<<<(n4 + BT - 1) / BT, BT>>>((float4*)pool, n4);
        int chunks = (N + 63) / 64;
        dim3 grid((chunks + 127) / 128, 13);
        k_pool<<<grid, 128>>>(bufB, batch32, b4, pool, N);
    }
    // ---- MLP head
    k_fc<<<(NG + BT - 1) / BT, BT>>>(pool, Wf1, bf1, Wf2, bf2, Wf3, bf3, out);
}